// round 1
// baseline (speedup 1.0000x reference)
#include <cuda_runtime.h>

// ---------------------------------------------------------------------------
// MultiHeadSelfAttention: x[4,2048,1024] -> out[4,2048,1024], fp32 baseline.
//   k1: qkv = x @ w_qkv + b_qkv            (8192 x 3072 x 1024 SGEMM)
//   k2: flash attention per (b,h)          (64 heads, 2048 seq, D=64)
//   k3: out = attn_out @ w_proj + b_proj   (8192 x 1024 x 1024 SGEMM)
// ---------------------------------------------------------------------------

#define EMBED   1024
#define HEADS   16
#define HDIM    64
#define BATCH   4
#define SEQ     2048
#define MROWS   (BATCH * SEQ)     // 8192
#define QKV_N   (3 * EMBED)       // 3072
#define ATT_SCALE 0.125f          // 64^-0.5

// Scratch (allocation-free rule: __device__ globals)
__device__ float g_qkv[MROWS * QKV_N];   // 96 MB
__device__ float g_att[MROWS * EMBED];   // 32 MB

// ---------------------------------------------------------------------------
// SGEMM: C[M,N] = A[M,K] @ B[K,N] + bias[N]
// BM=BN=128, BK=8, 256 threads, 8x8 register tile per thread.
// M,N multiples of 128; K multiple of 8. All pointers 16B aligned.
// ---------------------------------------------------------------------------
__global__ void __launch_bounds__(256)
sgemm_bias_kernel(const float* __restrict__ A, const float* __restrict__ B,
                  const float* __restrict__ bias, float* __restrict__ C,
                  int M, int N, int K)
{
    constexpr int BM = 128, BN = 128, BK = 8, TM = 8, TN = 8;
    __shared__ float As[BK][BM];
    __shared__ float Bs[BK][BN];

    const int tid = threadIdx.x;
    const int bx = blockIdx.x, by = blockIdx.y;
    const int tx = tid & 15;          // 0..15
    const int ty = tid >> 4;          // 0..15

    // A tile load: 128 rows x 8 k -> one float4 per thread
    const int aRow = tid >> 1;           // 0..127
    const int aCol = (tid & 1) * 4;      // 0 or 4
    // B tile load: 8 k-rows x 128 cols -> one float4 per thread
    const int bRow = tid >> 5;           // 0..7
    const int bCol = (tid & 31) * 4;     // 0..124

    const float* Aptr = A + (size_t)(by * BM + aRow) * K + aCol;
    const float* Bptr = B + (size_t)bRow * N + bx * BN + bCol;

    float acc[TM][TN] = {};

    for (int k0 = 0; k0 < K; k0 += BK) {
        float4 a4 = *(const float4*)(Aptr + k0);
        As[aCol + 0][aRow] = a4.x;
        As[aCol + 1][aRow] = a4.y;
        As[aCol + 2][aRow] = a4.z;
        As[aCol + 3][aRow] = a4.w;
        *(float4*)&Bs[bRow][bCol] = *(const float4*)(Bptr + (size_t)k0 * N);
        __syncthreads();

        #pragma unroll
        for (int k = 0; k < BK; ++k) {
            float ar[TM], br[TN];
            #pragma unroll
            for (int i = 0; i < TM; ++i) ar[i] = As[k][ty * TM + i];
            #pragma unroll
            for (int j = 0; j < TN; ++j) br[j] = Bs[k][tx * TN + j];
            #pragma unroll
            for (int i = 0; i < TM; ++i)
                #pragma unroll
                for (int j = 0; j < TN; ++j)
                    acc[i][j] += ar[i] * br[j];
        }
        __syncthreads();
    }

    const int row0 = by * BM + ty * TM;
    const int col0 = bx * BN + tx * TN;
    #pragma unroll
    for (int i = 0; i < TM; ++i) {
        #pragma unroll
        for (int j = 0; j < TN; j += 4) {
            float4 v;
            v.x = acc[i][j + 0] + bias[col0 + j + 0];
            v.y = acc[i][j + 1] + bias[col0 + j + 1];
            v.z = acc[i][j + 2] + bias[col0 + j + 2];
            v.w = acc[i][j + 3] + bias[col0 + j + 3];
            *(float4*)&C[(size_t)(row0 + i) * N + col0 + j] = v;
        }
    }
}

// ---------------------------------------------------------------------------
// Flash attention, fp32. Block = 64 queries of one (b,h); loops 32 KV tiles
// of 64. 256 threads; each thread owns a 4x4 microtile of S and of O.
// Online softmax: row stats in shared, P staged through shared for the PV GEMM.
// Dynamic smem: 4 * 64*65 floats + 3*64 floats = 67328 bytes.
// ---------------------------------------------------------------------------
#define FLASH_SMEM ((4 * 64 * 65 + 3 * 64) * 4)

__global__ void __launch_bounds__(256)
flash_attn_kernel(const float* __restrict__ qkv, float* __restrict__ out)
{
    const int qt = blockIdx.x;   // 0..31 query tile
    const int h  = blockIdx.y;   // 0..15
    const int b  = blockIdx.z;   // 0..3
    const int tid = threadIdx.x;
    const int tx = tid & 15;     // key/out-col group
    const int ty = tid >> 4;     // query-row group

    extern __shared__ float sm[];
    float (*Qs)[65] = (float(*)[65])(sm);
    float (*Ks)[65] = (float(*)[65])(sm + 64 * 65);
    float (*Vs)[65] = (float(*)[65])(sm + 2 * 64 * 65);
    float (*Ss)[65] = (float(*)[65])(sm + 3 * 64 * 65);
    float* m_s = sm + 4 * 64 * 65;
    float* l_s = m_s + 64;
    float* c_s = l_s + 64;

    const int rowQ0 = b * SEQ + qt * 64;   // global row of first query
    const int base  = h * HDIM;            // channel offset of this head

    // Load Q tile, pre-scaled
    for (int idx = tid; idx < 64 * 64; idx += 256) {
        int r = idx >> 6, d = idx & 63;
        Qs[r][d] = qkv[(size_t)(rowQ0 + r) * QKV_N + base + d] * ATT_SCALE;
    }
    if (tid < 64) { m_s[tid] = -1e30f; l_s[tid] = 0.f; }

    float o[4][4] = {};

    for (int kt = 0; kt < 32; ++kt) {
        __syncthreads();   // Q/stats ready (iter 0); prior O-update done (iter>0)

        const int rowK0 = b * SEQ + kt * 64;
        for (int idx = tid; idx < 64 * 64; idx += 256) {
            int r = idx >> 6, d = idx & 63;
            Ks[r][d] = qkv[(size_t)(rowK0 + r) * QKV_N + EMBED     + base + d];
            Vs[r][d] = qkv[(size_t)(rowK0 + r) * QKV_N + 2 * EMBED + base + d];
        }
        __syncthreads();

        // S = (Q*scale) @ K^T   (4x4 per thread)
        float s[4][4] = {};
        #pragma unroll 8
        for (int d = 0; d < 64; ++d) {
            float qr[4], kr[4];
            #pragma unroll
            for (int i = 0; i < 4; ++i) qr[i] = Qs[ty * 4 + i][d];
            #pragma unroll
            for (int j = 0; j < 4; ++j) kr[j] = Ks[tx * 4 + j][d];
            #pragma unroll
            for (int i = 0; i < 4; ++i)
                #pragma unroll
                for (int j = 0; j < 4; ++j)
                    s[i][j] += qr[i] * kr[j];
        }
        #pragma unroll
        for (int i = 0; i < 4; ++i)
            #pragma unroll
            for (int j = 0; j < 4; ++j)
                Ss[ty * 4 + i][tx * 4 + j] = s[i][j];
        __syncthreads();

        // Online softmax row update (one thread per query row)
        if (tid < 64) {
            float mOld = m_s[tid];
            float mNew = mOld;
            #pragma unroll 8
            for (int j = 0; j < 64; ++j) mNew = fmaxf(mNew, Ss[tid][j]);
            float corr = __expf(mOld - mNew);
            float sum = 0.f;
            #pragma unroll 8
            for (int j = 0; j < 64; ++j) {
                float p = __expf(Ss[tid][j] - mNew);
                Ss[tid][j] = p;
                sum += p;
            }
            m_s[tid] = mNew;
            l_s[tid] = l_s[tid] * corr + sum;
            c_s[tid] = corr;
        }
        __syncthreads();

        // O = O*corr + P @ V
        #pragma unroll
        for (int i = 0; i < 4; ++i) {
            float ci = c_s[ty * 4 + i];
            #pragma unroll
            for (int j = 0; j < 4; ++j) o[i][j] *= ci;
        }
        #pragma unroll 4
        for (int kk = 0; kk < 64; ++kk) {
            float pr[4], vr[4];
            #pragma unroll
            for (int i = 0; i < 4; ++i) pr[i] = Ss[ty * 4 + i][kk];
            #pragma unroll
            for (int j = 0; j < 4; ++j) vr[j] = Vs[kk][tx * 4 + j];
            #pragma unroll
            for (int i = 0; i < 4; ++i)
                #pragma unroll
                for (int j = 0; j < 4; ++j)
                    o[i][j] += pr[i] * vr[j];
        }
    }
    __syncthreads();

    // Normalize and write [B*N, C] with channel = h*64 + col
    #pragma unroll
    for (int i = 0; i < 4; ++i) {
        const int r = ty * 4 + i;
        const float inv = 1.f / l_s[r];
        float4 v;
        v.x = o[i][0] * inv;
        v.y = o[i][1] * inv;
        v.z = o[i][2] * inv;
        v.w = o[i][3] * inv;
        *(float4*)&out[(size_t)(rowQ0 + r) * EMBED + base + tx * 4] = v;
    }
}

// ---------------------------------------------------------------------------
// Launch (graph-capturable: kernel launches only)
// ---------------------------------------------------------------------------
extern "C" void kernel_launch(void* const* d_in, const int* in_sizes, int n_in,
                              void* d_out, int out_size)
{
    const float* x      = (const float*)d_in[0];
    const float* w_qkv  = (const float*)d_in[1];
    const float* b_qkv  = (const float*)d_in[2];
    const float* w_proj = (const float*)d_in[3];
    const float* b_proj = (const float*)d_in[4];
    float* out = (float*)d_out;

    float *qkv = nullptr, *att = nullptr;
    cudaGetSymbolAddress((void**)&qkv, g_qkv);
    cudaGetSymbolAddress((void**)&att, g_att);

    cudaFuncSetAttribute(flash_attn_kernel,
                         cudaFuncAttributeMaxDynamicSharedMemorySize, FLASH_SMEM);

    // k1: qkv = x @ w_qkv + b_qkv
    sgemm_bias_kernel<<<dim3(QKV_N / 128, MROWS / 128), 256>>>(
        x, w_qkv, b_qkv, qkv, MROWS, QKV_N, EMBED);

    // k2: flash attention
    flash_attn_kernel<<<dim3(SEQ / 64, HEADS, BATCH), 256, FLASH_SMEM>>>(qkv, att);

    // k3: out = att @ w_proj + b_proj
    sgemm_bias_kernel<<<dim3(EMBED / 128, MROWS / 128), 256>>>(
        att, w_proj, b_proj, out, MROWS, EMBED, EMBED);
}

// round 3
// speedup vs baseline: 1.3155x; 1.3155x over previous
#include <cuda_runtime.h>
#include <cuda_bf16.h>
#include <cstdint>

// ===========================================================================
// MultiHeadSelfAttention, sm_100 (plain target -> no tcgen05; use mma.sync).
//   s1: split x        -> xa  bf16 [8192 x 3072]  ([hi | lo | hi] along K)
//   s2: transpose+split w_qkv  -> wqkvT bf16 [3072 x 3072] ([hi | hi | lo])
//   s3: transpose+split w_proj -> wprojT bf16 [1024 x 3072]
//   k1: qkv = xa @ wqkvT^T + b_qkv   (HMMA bf16, fp32 accum)
//   k2: flash attention fp32 -> augmented bf16 atta
//   k3: out = atta @ wprojT^T + b_proj
// Split trick: A*B ~= Ahi*Bhi + Alo*Bhi + Ahi*Blo  (one K=3072 bf16 GEMM)
// ===========================================================================

#define EMBED   1024
#define HEADS   16
#define HDIM    64
#define BATCH   4
#define SEQ     2048
#define MROWS   (BATCH * SEQ)     // 8192
#define QKV_N   (3 * EMBED)       // 3072
#define KAUG    (3 * EMBED)       // 3072
#define ATT_SCALE 0.125f

__device__ float          g_qkv[(size_t)MROWS * QKV_N];      // 96 MB fp32
__device__ __nv_bfloat16  g_xa[(size_t)MROWS * KAUG];        // 48 MB
__device__ __nv_bfloat16  g_atta[(size_t)MROWS * KAUG];      // 48 MB
__device__ __nv_bfloat16  g_wqkvT[(size_t)QKV_N * KAUG];     // 18 MB
__device__ __nv_bfloat16  g_wprojT[(size_t)EMBED * KAUG];    //  6 MB

// ---------------------------------------------------------------------------
// helpers
// ---------------------------------------------------------------------------
__device__ __forceinline__ uint32_t smem_u32(const void* p) {
    uint32_t a;
    asm("{ .reg .u64 t; cvta.to.shared.u64 t, %1; cvt.u32.u64 %0, t; }"
        : "=r"(a) : "l"(p));
    return a;
}
__device__ __forceinline__ void ldsm_x4(uint32_t& r0, uint32_t& r1,
                                        uint32_t& r2, uint32_t& r3, uint32_t addr) {
    asm volatile("ldmatrix.sync.aligned.m8n8.x4.shared.b16 {%0,%1,%2,%3}, [%4];"
                 : "=r"(r0), "=r"(r1), "=r"(r2), "=r"(r3) : "r"(addr));
}
__device__ __forceinline__ void mma_bf16(float* c, uint32_t a0, uint32_t a1,
                                         uint32_t a2, uint32_t a3,
                                         uint32_t b0, uint32_t b1) {
    asm volatile(
        "mma.sync.aligned.m16n8k16.row.col.f32.bf16.bf16.f32 "
        "{%0,%1,%2,%3}, {%4,%5,%6,%7}, {%8,%9}, {%0,%1,%2,%3};"
        : "+f"(c[0]), "+f"(c[1]), "+f"(c[2]), "+f"(c[3])
        : "r"(a0), "r"(a1), "r"(a2), "r"(a3), "r"(b0), "r"(b1));
}
#define CP_ASYNC16(smem, gptr) \
    asm volatile("cp.async.cg.shared.global [%0], [%1], 16;" :: "r"(smem), "l"(gptr))
#define CP_COMMIT() asm volatile("cp.async.commit_group;" ::: "memory")
#define CP_WAIT0()  asm volatile("cp.async.wait_group 0;" ::: "memory")
#define CP_WAIT1()  asm volatile("cp.async.wait_group 1;" ::: "memory")

// smem tile: 128 rows x 32 bf16 (64 B/row); chunk swizzle keeps ldmatrix
// conflict-free: chunk' = chunk ^ ((row>>1)&3)  (bijective per 128B phase)
__device__ __forceinline__ uint32_t tile_off(int r, int c) {
    return (uint32_t)(r * 64 + ((c ^ ((r >> 1) & 3)) << 4));
}

// ---------------------------------------------------------------------------
// bf16 split helpers
// ---------------------------------------------------------------------------
__device__ __forceinline__ void split_hl(float v, __nv_bfloat16& hi, __nv_bfloat16& lo) {
    hi = __float2bfloat16_rn(v);
    lo = __float2bfloat16_rn(v - __bfloat162float(hi));
}
__device__ __forceinline__ uint32_t pack2bf(__nv_bfloat16 a, __nv_bfloat16 b) {
    __nv_bfloat162 p(a, b);
    return *reinterpret_cast<uint32_t*>(&p);
}

// ---------------------------------------------------------------------------
// s1: split x -> xa [hi | lo | hi]
// ---------------------------------------------------------------------------
__global__ void __launch_bounds__(256)
split_x_kernel(const float* __restrict__ x, __nv_bfloat16* __restrict__ xa)
{
    const int row = blockIdx.x;
    const int c = threadIdx.x * 4;
    float4 v = *(const float4*)(x + (size_t)row * EMBED + c);
    __nv_bfloat16 h0,h1,h2,h3,l0,l1,l2,l3;
    split_hl(v.x, h0, l0); split_hl(v.y, h1, l1);
    split_hl(v.z, h2, l2); split_hl(v.w, h3, l3);
    const size_t o = (size_t)row * KAUG + c;
    uint2 uh; uh.x = pack2bf(h0,h1); uh.y = pack2bf(h2,h3);
    uint2 ul; ul.x = pack2bf(l0,l1); ul.y = pack2bf(l2,l3);
    *(uint2*)(xa + o)           = uh;
    *(uint2*)(xa + o + EMBED)   = ul;
    *(uint2*)(xa + o + 2*EMBED) = uh;
}

// ---------------------------------------------------------------------------
// s2/s3: W [K x N] fp32 -> Bp [N x 3K] bf16 ([hi | hi | lo])
// ---------------------------------------------------------------------------
__global__ void __launch_bounds__(256)
transpose_split_kernel(const float* __restrict__ W, __nv_bfloat16* __restrict__ Bp,
                       int K, int N)
{
    __shared__ float t[32][33];
    const int n0 = blockIdx.x * 32, k0 = blockIdx.y * 32;
    const int tx = threadIdx.x, ty = threadIdx.y;
    #pragma unroll
    for (int i = 0; i < 4; ++i)
        t[ty + 8*i][tx] = W[(size_t)(k0 + ty + 8*i) * N + n0 + tx];
    __syncthreads();
    #pragma unroll
    for (int i = 0; i < 4; ++i) {
        const int n = ty + 8*i;
        float v = t[tx][n];
        __nv_bfloat16 hi, lo;
        split_hl(v, hi, lo);
        const size_t ro = (size_t)(n0 + n) * (3*K);
        Bp[ro + k0 + tx]       = hi;
        Bp[ro + K + k0 + tx]   = hi;
        Bp[ro + 2*K + k0 + tx] = lo;
    }
}

// ---------------------------------------------------------------------------
// HMMA GEMM: C[M,N] = A[M,K]bf16 @ B[N,K]bf16^T + bias
// 128x128x32 tile, 256 thr (8 warps 2x4), warp tile 64x32, cp.async 2-stage.
// ---------------------------------------------------------------------------
__global__ void __launch_bounds__(256)
mma_gemm_kernel(const __nv_bfloat16* __restrict__ A, const __nv_bfloat16* __restrict__ B,
                const float* __restrict__ bias, float* __restrict__ C,
                int M, int N, int K)
{
    __shared__ __align__(1024) uint8_t smA[2][8192];
    __shared__ __align__(1024) uint8_t smB[2][8192];

    const int tid  = threadIdx.x;
    const int wid  = tid >> 5;
    const int lane = tid & 31;
    const int bx = blockIdx.x, by = blockIdx.y;
    const int warp_m = wid & 1;          // 0..1
    const int warp_n = wid >> 1;         // 0..3

    const size_t Ks = (size_t)K;
    const __nv_bfloat16* Ab = A + (size_t)(by * 128) * Ks;
    const __nv_bfloat16* Bb = B + (size_t)(bx * 128) * Ks;

    // per-thread load slots: 512 16B-chunks per tile; thread does 2 (A) + 2 (B)
    const int r0 = tid >> 1;                 // rows r0, r0+... (idx = tid + 256*j)
    // issue cp.async for tile `kt` into buffer `buf`
    auto load_tile = [&](int kt, int buf) {
        const int k0 = kt * 32;
        #pragma unroll
        for (int j = 0; j < 2; ++j) {
            const int idx = tid + 256 * j;
            const int r = idx >> 2, c = idx & 3;
            const uint32_t sa = smem_u32(&smA[buf][0]) + tile_off(r, c);
            const uint32_t sb = smem_u32(&smB[buf][0]) + tile_off(r, c);
            CP_ASYNC16(sa, Ab + (size_t)r * Ks + k0 + c * 8);
            CP_ASYNC16(sb, Bb + (size_t)r * Ks + k0 + c * 8);
        }
        CP_COMMIT();
    };

    float acc[4][4][4] = {};   // [mf][nf][4]

    const int T = K >> 5;
    load_tile(0, 0);

    for (int t = 0; t < T; ++t) {
        const int cur = t & 1;
        if (t + 1 < T) { load_tile(t + 1, cur ^ 1); CP_WAIT1(); }
        else           { CP_WAIT0(); }
        __syncthreads();

        const uint32_t baseA = smem_u32(&smA[cur][0]);
        const uint32_t baseB = smem_u32(&smB[cur][0]);

        #pragma unroll
        for (int ks = 0; ks < 2; ++ks) {
            uint32_t a[4][4];
            #pragma unroll
            for (int mf = 0; mf < 4; ++mf) {
                const int r = warp_m * 64 + mf * 16 + (lane & 15);
                const int c = ks * 2 + (lane >> 4);
                ldsm_x4(a[mf][0], a[mf][1], a[mf][2], a[mf][3], baseA + tile_off(r, c));
            }
            uint32_t b[2][4];
            #pragma unroll
            for (int np = 0; np < 2; ++np) {
                const int r = warp_n * 32 + np * 16 + (lane & 15);
                const int c = ks * 2 + (lane >> 4);
                ldsm_x4(b[np][0], b[np][1], b[np][2], b[np][3], baseB + tile_off(r, c));
            }
            #pragma unroll
            for (int mf = 0; mf < 4; ++mf)
                #pragma unroll
                for (int nf = 0; nf < 4; ++nf) {
                    const int np = nf >> 1, hl = nf & 1;
                    mma_bf16(acc[mf][nf], a[mf][0], a[mf][1], a[mf][2], a[mf][3],
                             b[np][0 + hl], b[np][2 + hl]);
                }
        }
        __syncthreads();
    }

    // epilogue
    const int g = lane >> 2;            // row group 0..7
    const int cl = (lane & 3) * 2;      // col pair
    #pragma unroll
    for (int mf = 0; mf < 4; ++mf) {
        const int mrow = by * 128 + warp_m * 64 + mf * 16 + g;
        #pragma unroll
        for (int nf = 0; nf < 4; ++nf) {
            const int col = bx * 128 + warp_n * 32 + nf * 8 + cl;
            const float b0 = bias[col], b1 = bias[col + 1];
            float2 v0 = { acc[mf][nf][0] + b0, acc[mf][nf][1] + b1 };
            float2 v1 = { acc[mf][nf][2] + b0, acc[mf][nf][3] + b1 };
            *(float2*)(C + (size_t)mrow * N + col)       = v0;
            *(float2*)(C + (size_t)(mrow + 8) * N + col) = v1;
        }
    }
}

// ---------------------------------------------------------------------------
// k2: flash attention fp32 -> augmented bf16 epilogue
// ---------------------------------------------------------------------------
#define FLASH_SMEM ((4 * 64 * 65 + 3 * 64) * 4)

__global__ void __launch_bounds__(256)
flash_attn_kernel(const float* __restrict__ qkv, __nv_bfloat16* __restrict__ atta)
{
    const int qt = blockIdx.x, h = blockIdx.y, b = blockIdx.z;
    const int tid = threadIdx.x;
    const int tx = tid & 15, ty = tid >> 4;

    extern __shared__ float fsm[];
    float (*Qs)[65]  = (float(*)[65])(fsm);
    float (*Ks2)[65] = (float(*)[65])(fsm + 64*65);
    float (*Vs)[65]  = (float(*)[65])(fsm + 2*64*65);
    float (*Ss)[65]  = (float(*)[65])(fsm + 3*64*65);
    float* m_s = fsm + 4*64*65;
    float* l_s = m_s + 64;
    float* c_s = l_s + 64;

    const int rowQ0 = b * SEQ + qt * 64;
    const int base = h * HDIM;

    for (int idx = tid; idx < 64*64; idx += 256) {
        int r = idx >> 6, d = idx & 63;
        Qs[r][d] = qkv[(size_t)(rowQ0 + r) * QKV_N + base + d] * ATT_SCALE;
    }
    if (tid < 64) { m_s[tid] = -1e30f; l_s[tid] = 0.f; }

    float o[4][4] = {};

    for (int kt = 0; kt < 32; ++kt) {
        __syncthreads();
        const int rowK0 = b * SEQ + kt * 64;
        for (int idx = tid; idx < 64*64; idx += 256) {
            int r = idx >> 6, d = idx & 63;
            Ks2[r][d] = qkv[(size_t)(rowK0 + r) * QKV_N + EMBED   + base + d];
            Vs[r][d]  = qkv[(size_t)(rowK0 + r) * QKV_N + 2*EMBED + base + d];
        }
        __syncthreads();

        float s[4][4] = {};
        #pragma unroll 8
        for (int d = 0; d < 64; ++d) {
            float qr[4], kr[4];
            #pragma unroll
            for (int i = 0; i < 4; ++i) qr[i] = Qs[ty*4+i][d];
            #pragma unroll
            for (int j = 0; j < 4; ++j) kr[j] = Ks2[tx*4+j][d];
            #pragma unroll
            for (int i = 0; i < 4; ++i)
                #pragma unroll
                for (int j = 0; j < 4; ++j)
                    s[i][j] += qr[i] * kr[j];
        }
        #pragma unroll
        for (int i = 0; i < 4; ++i)
            #pragma unroll
            for (int j = 0; j < 4; ++j)
                Ss[ty*4+i][tx*4+j] = s[i][j];
        __syncthreads();

        if (tid < 64) {
            float mOld = m_s[tid], mNew = mOld;
            #pragma unroll 8
            for (int j = 0; j < 64; ++j) mNew = fmaxf(mNew, Ss[tid][j]);
            float corr = __expf(mOld - mNew), sum = 0.f;
            #pragma unroll 8
            for (int j = 0; j < 64; ++j) {
                float p = __expf(Ss[tid][j] - mNew);
                Ss[tid][j] = p;
                sum += p;
            }
            m_s[tid] = mNew;
            l_s[tid] = l_s[tid] * corr + sum;
            c_s[tid] = corr;
        }
        __syncthreads();

        #pragma unroll
        for (int i = 0; i < 4; ++i) {
            float ci = c_s[ty*4+i];
            #pragma unroll
            for (int j = 0; j < 4; ++j) o[i][j] *= ci;
        }
        #pragma unroll 4
        for (int kk = 0; kk < 64; ++kk) {
            float pr[4], vr[4];
            #pragma unroll
            for (int i = 0; i < 4; ++i) pr[i] = Ss[ty*4+i][kk];
            #pragma unroll
            for (int j = 0; j < 4; ++j) vr[j] = Vs[kk][tx*4+j];
            #pragma unroll
            for (int i = 0; i < 4; ++i)
                #pragma unroll
                for (int j = 0; j < 4; ++j)
                    o[i][j] += pr[i] * vr[j];
        }
    }
    __syncthreads();

    #pragma unroll
    for (int i = 0; i < 4; ++i) {
        const int r = ty*4 + i;
        const float inv = 1.f / l_s[r];
        float v0 = o[i][0]*inv, v1 = o[i][1]*inv, v2 = o[i][2]*inv, v3 = o[i][3]*inv;
        __nv_bfloat16 h0,h1,h2,h3,l0,l1,l2,l3;
        split_hl(v0, h0, l0); split_hl(v1, h1, l1);
        split_hl(v2, h2, l2); split_hl(v3, h3, l3);
        const size_t ro = (size_t)(rowQ0 + r) * KAUG + base + tx*4;
        uint2 uh; uh.x = pack2bf(h0,h1); uh.y = pack2bf(h2,h3);
        uint2 ul; ul.x = pack2bf(l0,l1); ul.y = pack2bf(l2,l3);
        *(uint2*)(atta + ro)           = uh;
        *(uint2*)(atta + ro + EMBED)   = ul;
        *(uint2*)(atta + ro + 2*EMBED) = uh;
    }
}

// ---------------------------------------------------------------------------
// Launch
// ---------------------------------------------------------------------------
extern "C" void kernel_launch(void* const* d_in, const int* in_sizes, int n_in,
                              void* d_out, int out_size)
{
    const float* x      = (const float*)d_in[0];
    const float* w_qkv  = (const float*)d_in[1];
    const float* b_qkv  = (const float*)d_in[2];
    const float* w_proj = (const float*)d_in[3];
    const float* b_proj = (const float*)d_in[4];
    float* out = (float*)d_out;

    float *qkv = nullptr;
    __nv_bfloat16 *xa = nullptr, *atta = nullptr, *wqkvT = nullptr, *wprojT = nullptr;
    cudaGetSymbolAddress((void**)&qkv,    g_qkv);
    cudaGetSymbolAddress((void**)&xa,     g_xa);
    cudaGetSymbolAddress((void**)&atta,   g_atta);
    cudaGetSymbolAddress((void**)&wqkvT,  g_wqkvT);
    cudaGetSymbolAddress((void**)&wprojT, g_wprojT);

    cudaFuncSetAttribute(flash_attn_kernel,
                         cudaFuncAttributeMaxDynamicSharedMemorySize, FLASH_SMEM);

    split_x_kernel<<<MROWS, 256>>>(x, xa);
    transpose_split_kernel<<<dim3(QKV_N/32, EMBED/32), dim3(32,8)>>>(w_qkv, wqkvT, EMBED, QKV_N);
    transpose_split_kernel<<<dim3(EMBED/32, EMBED/32), dim3(32,8)>>>(w_proj, wprojT, EMBED, EMBED);

    mma_gemm_kernel<<<dim3(QKV_N/128, MROWS/128), 256>>>(
        xa, wqkvT, b_qkv, qkv, MROWS, QKV_N, KAUG);

    flash_attn_kernel<<<dim3(SEQ/64, HEADS, BATCH), 256, FLASH_SMEM>>>(qkv, atta);

    mma_gemm_kernel<<<dim3(EMBED/128, MROWS/128), 256>>>(
        atta, wprojT, b_proj, out, MROWS, EMBED, KAUG);
}

// round 4
// speedup vs baseline: 2.6907x; 2.0454x over previous
#include <cuda_runtime.h>
#include <cuda_bf16.h>
#include <cstdint>

// ===========================================================================
// MultiHeadSelfAttention, sm_100 (mma.sync HMMA path everywhere).
//   s1: split x -> xa bf16 [8192 x 3072] ([hi|lo|hi])
//   s2/s3: transpose+split weights -> [N x 3K] bf16 ([hi|hi|lo])
//   k1: qkv GEMM -> split bf16 planes: qhi/qlo,khi/klo [bh][n][64],
//       vhiT/vloT [bh][d][n] (transposed). Q pre-scaled by 0.125*log2(e).
//   k2: flash attention on HMMA with chunk-remapped split products
//       (qhi*khi + qlo*khi + qhi*klo, and phi*vhi + plo*vhi + phi*vlo),
//       exp2f softmax; writes augmented atta [8192 x 3072].
//   k3: out = atta @ wprojT^T + b_proj.
// ===========================================================================

#define EMBED   1024
#define HEADS   16
#define HDIM    64
#define BATCH   4
#define SEQ     2048
#define MROWS   (BATCH * SEQ)     // 8192
#define QKV_N   (3 * EMBED)       // 3072
#define KAUG    (3 * EMBED)       // 3072
#define NBH     (BATCH * HEADS)   // 64
#define QSC     (0.125f * 1.44269504f)

__device__ __nv_bfloat16  g_xa[(size_t)MROWS * KAUG];       // 48 MB
__device__ __nv_bfloat16  g_atta[(size_t)MROWS * KAUG];     // 48 MB
__device__ __nv_bfloat16  g_wqkvT[(size_t)QKV_N * KAUG];    // 18 MB
__device__ __nv_bfloat16  g_wprojT[(size_t)EMBED * KAUG];   //  6 MB
__device__ __nv_bfloat16  g_qhi[(size_t)NBH * SEQ * HDIM];  // 16 MB each
__device__ __nv_bfloat16  g_qlo[(size_t)NBH * SEQ * HDIM];
__device__ __nv_bfloat16  g_khi[(size_t)NBH * SEQ * HDIM];
__device__ __nv_bfloat16  g_klo[(size_t)NBH * SEQ * HDIM];
__device__ __nv_bfloat16  g_vhiT[(size_t)NBH * HDIM * SEQ];
__device__ __nv_bfloat16  g_vloT[(size_t)NBH * HDIM * SEQ];

// ---------------------------------------------------------------------------
// helpers
// ---------------------------------------------------------------------------
__device__ __forceinline__ uint32_t smem_u32(const void* p) {
    uint32_t a;
    asm("{ .reg .u64 t; cvta.to.shared.u64 t, %1; cvt.u32.u64 %0, t; }"
        : "=r"(a) : "l"(p));
    return a;
}
__device__ __forceinline__ void ldsm_x4(uint32_t& r0, uint32_t& r1,
                                        uint32_t& r2, uint32_t& r3, uint32_t addr) {
    asm volatile("ldmatrix.sync.aligned.m8n8.x4.shared.b16 {%0,%1,%2,%3}, [%4];"
                 : "=r"(r0), "=r"(r1), "=r"(r2), "=r"(r3) : "r"(addr));
}
__device__ __forceinline__ void mma_bf16(float* c, uint32_t a0, uint32_t a1,
                                         uint32_t a2, uint32_t a3,
                                         uint32_t b0, uint32_t b1) {
    asm volatile(
        "mma.sync.aligned.m16n8k16.row.col.f32.bf16.bf16.f32 "
        "{%0,%1,%2,%3}, {%4,%5,%6,%7}, {%8,%9}, {%0,%1,%2,%3};"
        : "+f"(c[0]), "+f"(c[1]), "+f"(c[2]), "+f"(c[3])
        : "r"(a0), "r"(a1), "r"(a2), "r"(a3), "r"(b0), "r"(b1));
}
#define CP_ASYNC16(smem, gptr) \
    asm volatile("cp.async.cg.shared.global [%0], [%1], 16;" :: "r"(smem), "l"(gptr))
#define CP_COMMIT() asm volatile("cp.async.commit_group;" ::: "memory")
#define CP_WAIT0()  asm volatile("cp.async.wait_group 0;" ::: "memory")
#define CP_WAIT1()  asm volatile("cp.async.wait_group 1;" ::: "memory")

// GEMM tile (64B rows): chunk' = chunk ^ ((row>>1)&3)
__device__ __forceinline__ uint32_t tile_off(int r, int c) {
    return (uint32_t)(r * 64 + ((c ^ ((r >> 1) & 3)) << 4));
}
// Flash tile (256B rows, 16 chunks): chunk' = chunk ^ (row & 7)
__device__ __forceinline__ uint32_t foff(int r, int c) {
    return (uint32_t)(r * 256 + ((c ^ (r & 7)) << 4));
}

__device__ __forceinline__ void split_hl(float v, __nv_bfloat16& hi, __nv_bfloat16& lo) {
    hi = __float2bfloat16_rn(v);
    lo = __float2bfloat16_rn(v - __bfloat162float(hi));
}
__device__ __forceinline__ uint32_t pack2bf(__nv_bfloat16 a, __nv_bfloat16 b) {
    __nv_bfloat162 p(a, b);
    return *reinterpret_cast<uint32_t*>(&p);
}

// ---------------------------------------------------------------------------
// s1: split x -> xa [hi | lo | hi]
// ---------------------------------------------------------------------------
__global__ void __launch_bounds__(256)
split_x_kernel(const float* __restrict__ x, __nv_bfloat16* __restrict__ xa)
{
    const int row = blockIdx.x;
    const int c = threadIdx.x * 4;
    float4 v = *(const float4*)(x + (size_t)row * EMBED + c);
    __nv_bfloat16 h0,h1,h2,h3,l0,l1,l2,l3;
    split_hl(v.x, h0, l0); split_hl(v.y, h1, l1);
    split_hl(v.z, h2, l2); split_hl(v.w, h3, l3);
    const size_t o = (size_t)row * KAUG + c;
    uint2 uh; uh.x = pack2bf(h0,h1); uh.y = pack2bf(h2,h3);
    uint2 ul; ul.x = pack2bf(l0,l1); ul.y = pack2bf(l2,l3);
    *(uint2*)(xa + o)           = uh;
    *(uint2*)(xa + o + EMBED)   = ul;
    *(uint2*)(xa + o + 2*EMBED) = uh;
}

// ---------------------------------------------------------------------------
// s2/s3: W [K x N] fp32 -> Bp [N x 3K] bf16 ([hi | hi | lo])
// ---------------------------------------------------------------------------
__global__ void __launch_bounds__(256)
transpose_split_kernel(const float* __restrict__ W, __nv_bfloat16* __restrict__ Bp,
                       int K, int N)
{
    __shared__ float t[32][33];
    const int n0 = blockIdx.x * 32, k0 = blockIdx.y * 32;
    const int tx = threadIdx.x, ty = threadIdx.y;
    #pragma unroll
    for (int i = 0; i < 4; ++i)
        t[ty + 8*i][tx] = W[(size_t)(k0 + ty + 8*i) * N + n0 + tx];
    __syncthreads();
    #pragma unroll
    for (int i = 0; i < 4; ++i) {
        const int n = ty + 8*i;
        float v = t[tx][n];
        __nv_bfloat16 hi, lo;
        split_hl(v, hi, lo);
        const size_t ro = (size_t)(n0 + n) * (3*K);
        Bp[ro + k0 + tx]       = hi;
        Bp[ro + K + k0 + tx]   = hi;
        Bp[ro + 2*K + k0 + tx] = lo;
    }
}

// ---------------------------------------------------------------------------
// HMMA GEMM: 128x128x32 tile, 8 warps (2x4), cp.async 2-stage.
// MODE 0: C = A@B^T + bias (fp32 out).  MODE 1: qkv epilogue -> split planes.
// ---------------------------------------------------------------------------
template<int MODE>
__global__ void __launch_bounds__(256)
mma_gemm_kernel(const __nv_bfloat16* __restrict__ A, const __nv_bfloat16* __restrict__ B,
                const float* __restrict__ bias, float* __restrict__ C,
                __nv_bfloat16* __restrict__ qh, __nv_bfloat16* __restrict__ ql,
                __nv_bfloat16* __restrict__ kh, __nv_bfloat16* __restrict__ kl,
                __nv_bfloat16* __restrict__ vh, __nv_bfloat16* __restrict__ vl,
                int M, int N, int K)
{
    __shared__ __align__(1024) uint8_t smA[2][8192];
    __shared__ __align__(1024) uint8_t smB[2][8192];

    const int tid  = threadIdx.x;
    const int wid  = tid >> 5;
    const int lane = tid & 31;
    const int bx = blockIdx.x, by = blockIdx.y;
    const int warp_m = wid & 1;
    const int warp_n = wid >> 1;

    const size_t Ks = (size_t)K;
    const __nv_bfloat16* Ab = A + (size_t)(by * 128) * Ks;
    const __nv_bfloat16* Bb = B + (size_t)(bx * 128) * Ks;

    auto load_tile = [&](int kt, int buf) {
        const int k0 = kt * 32;
        #pragma unroll
        for (int j = 0; j < 2; ++j) {
            const int idx = tid + 256 * j;
            const int r = idx >> 2, c = idx & 3;
            const uint32_t sa = smem_u32(&smA[buf][0]) + tile_off(r, c);
            const uint32_t sb = smem_u32(&smB[buf][0]) + tile_off(r, c);
            CP_ASYNC16(sa, Ab + (size_t)r * Ks + k0 + c * 8);
            CP_ASYNC16(sb, Bb + (size_t)r * Ks + k0 + c * 8);
        }
        CP_COMMIT();
    };

    float acc[4][4][4] = {};

    const int T = K >> 5;
    load_tile(0, 0);

    for (int t = 0; t < T; ++t) {
        const int cur = t & 1;
        if (t + 1 < T) { load_tile(t + 1, cur ^ 1); CP_WAIT1(); }
        else           { CP_WAIT0(); }
        __syncthreads();

        const uint32_t baseA = smem_u32(&smA[cur][0]);
        const uint32_t baseB = smem_u32(&smB[cur][0]);

        #pragma unroll
        for (int ks = 0; ks < 2; ++ks) {
            uint32_t a[4][4];
            #pragma unroll
            for (int mf = 0; mf < 4; ++mf) {
                const int r = warp_m * 64 + mf * 16 + (lane & 15);
                const int c = ks * 2 + (lane >> 4);
                ldsm_x4(a[mf][0], a[mf][1], a[mf][2], a[mf][3], baseA + tile_off(r, c));
            }
            uint32_t b[2][4];
            #pragma unroll
            for (int np = 0; np < 2; ++np) {
                const int r = warp_n * 32 + np * 16 + (lane & 15);
                const int c = ks * 2 + (lane >> 4);
                ldsm_x4(b[np][0], b[np][1], b[np][2], b[np][3], baseB + tile_off(r, c));
            }
            #pragma unroll
            for (int mf = 0; mf < 4; ++mf)
                #pragma unroll
                for (int nf = 0; nf < 4; ++nf) {
                    const int np = nf >> 1, hl = nf & 1;
                    mma_bf16(acc[mf][nf], a[mf][0], a[mf][1], a[mf][2], a[mf][3],
                             b[np][0 + hl], b[np][2 + hl]);
                }
        }
        __syncthreads();
    }

    const int g  = lane >> 2;
    const int cl = (lane & 3) * 2;
    #pragma unroll
    for (int mf = 0; mf < 4; ++mf) {
        const int mrow = by * 128 + warp_m * 64 + mf * 16 + g;
        #pragma unroll
        for (int nf = 0; nf < 4; ++nf) {
            const int col = bx * 128 + warp_n * 32 + nf * 8 + cl;
            const float b0 = bias[col], b1 = bias[col + 1];
            float v[4] = { acc[mf][nf][0] + b0, acc[mf][nf][1] + b1,
                           acc[mf][nf][2] + b0, acc[mf][nf][3] + b1 };
            if constexpr (MODE == 0) {
                *(float2*)(C + (size_t)mrow * N + col)       = make_float2(v[0], v[1]);
                *(float2*)(C + (size_t)(mrow + 8) * N + col) = make_float2(v[2], v[3]);
            } else {
                const int which = col >> 10;           // 0=q 1=k 2=v
                const int h = (col >> 6) & 15;
                const int d = col & 63;
                const int bb = mrow >> 11;
                const int n0 = mrow & 2047;
                if (which == 0) { v[0]*=QSC; v[1]*=QSC; v[2]*=QSC; v[3]*=QSC; }
                #pragma unroll
                for (int rr = 0; rr < 2; ++rr) {
                    const int n = n0 + rr * 8;
                    __nv_bfloat16 h0,l0,h1,l1;
                    split_hl(v[rr*2+0], h0, l0);
                    split_hl(v[rr*2+1], h1, l1);
                    if (which < 2) {
                        const size_t base = (size_t)(bb*16 + h) * (SEQ*HDIM)
                                          + (size_t)n * HDIM + d;
                        __nv_bfloat16* PH = which ? kh : qh;
                        __nv_bfloat16* PL = which ? kl : ql;
                        *(uint32_t*)(PH + base) = pack2bf(h0, h1);
                        *(uint32_t*)(PL + base) = pack2bf(l0, l1);
                    } else {
                        const size_t base = (size_t)(bb*16 + h) * (SEQ*HDIM)
                                          + (size_t)d * SEQ + n;
                        vh[base]       = h0;  vh[base + SEQ] = h1;
                        vl[base]       = l0;  vl[base + SEQ] = l1;
                    }
                }
            }
        }
    }
}

// ---------------------------------------------------------------------------
// k2: flash attention on HMMA. 64 queries/block, 128 thr (4 warps, 2x2).
// smem: Qa/Ka/Va/Pa 16KB each ([hi|lo] 64x128 bf16, 256B rows) + stats.
// 12 k-steps per gemm via chunk remap: AU/BU select 32B units.
// ---------------------------------------------------------------------------
#define FLASH_SMEM (4 * 16384 + 1536)

__global__ void __launch_bounds__(128)
flash_mma_kernel(const __nv_bfloat16* __restrict__ qhi, const __nv_bfloat16* __restrict__ qlo,
                 const __nv_bfloat16* __restrict__ khi, const __nv_bfloat16* __restrict__ klo,
                 const __nv_bfloat16* __restrict__ vhiT, const __nv_bfloat16* __restrict__ vloT,
                 __nv_bfloat16* __restrict__ atta)
{
    extern __shared__ __align__(1024) uint8_t fsm[];
    uint8_t* Pa_c = fsm + 49152;
    float* pmax = (float*)(fsm + 65536);     // [2][64]
    float* psum = pmax + 128;                // [2][64]
    float* m_s  = psum + 128;                // [64]
    float* l_s  = m_s + 64;                  // [64]

    const uint32_t sbase = smem_u32(fsm);
    const uint32_t qa_u = sbase, ka_u = sbase + 16384,
                   va_u = sbase + 32768, pa_u = sbase + 49152;

    const int tid  = threadIdx.x;
    const int wid  = tid >> 5;
    const int lane = tid & 31;
    const int warpM = wid >> 1;      // q-half
    const int warpN = wid & 1;       // key/dim-half
    const int g  = lane >> 2;
    const int qd = lane & 3;

    const int qt = blockIdx.x, bh = blockIdx.y;
    const int q0 = qt * 64;

    // load Q [64 x (qhi|qlo)]
    {
        const size_t qbase = ((size_t)bh * SEQ + q0) * HDIM;
        for (int i = tid; i < 1024; i += 128) {
            const int r = i >> 4, c = i & 15;
            const __nv_bfloat16* src = (c < 8 ? qhi : qlo) + qbase + r * HDIM + (c & 7) * 8;
            CP_ASYNC16(qa_u + foff(r, c), src);
        }
        CP_COMMIT();
    }
    if (tid < 64) { m_s[tid] = -1e30f; l_s[tid] = 0.f; }

    // k-step -> (A 32B-unit, B 32B-unit): hi*hi, lo*hi, hi*lo
    const int AU[12] = {0,1,2,3, 4,5,6,7, 0,1,2,3};
    const int BU[12] = {0,1,2,3, 0,1,2,3, 4,5,6,7};

    float oacc[2][4][4] = {};

    for (int kt = 0; kt < 32; ++kt) {
        __syncthreads();   // prior iter done with Ka/Va/Pa (and stats updated)

        // load K/V tile
        const size_t kbase = ((size_t)bh * SEQ + kt * 64) * HDIM;
        for (int i = tid; i < 1024; i += 128) {
            const int r = i >> 4, c = i & 15;
            CP_ASYNC16(ka_u + foff(r, c),
                       (c < 8 ? khi : klo) + kbase + r * HDIM + (c & 7) * 8);
            CP_ASYNC16(va_u + foff(r, c),
                       (c < 8 ? vhiT : vloT) + (size_t)(bh * HDIM + r) * SEQ
                                             + kt * 64 + (c & 7) * 8);
        }
        CP_COMMIT(); CP_WAIT0();
        __syncthreads();

        // ---- S = Qa @ Ka^T (12 remapped k-steps) ----
        float sacc[2][4][4] = {};
        #pragma unroll
        for (int s = 0; s < 12; ++s) {
            uint32_t a[2][4], bfr[2][4];
            #pragma unroll
            for (int m = 0; m < 2; ++m)
                ldsm_x4(a[m][0], a[m][1], a[m][2], a[m][3],
                        qa_u + foff(warpM*32 + m*16 + (lane & 15), 2*AU[s] + (lane >> 4)));
            #pragma unroll
            for (int np = 0; np < 2; ++np)
                ldsm_x4(bfr[np][0], bfr[np][1], bfr[np][2], bfr[np][3],
                        ka_u + foff(warpN*32 + np*16 + (lane & 15), 2*BU[s] + (lane >> 4)));
            #pragma unroll
            for (int m = 0; m < 2; ++m)
                #pragma unroll
                for (int nf = 0; nf < 4; ++nf)
                    mma_bf16(sacc[m][nf], a[m][0], a[m][1], a[m][2], a[m][3],
                             bfr[nf >> 1][nf & 1], bfr[nf >> 1][2 + (nf & 1)]);
        }

        // ---- softmax ----
        float tmax[2][2];
        #pragma unroll
        for (int m = 0; m < 2; ++m)
            #pragma unroll
            for (int gg = 0; gg < 2; ++gg) {
                float mx = -1e30f;
                #pragma unroll
                for (int nf = 0; nf < 4; ++nf)
                    mx = fmaxf(mx, fmaxf(sacc[m][nf][gg*2], sacc[m][nf][gg*2+1]));
                tmax[m][gg] = mx;
            }
        #pragma unroll
        for (int o = 1; o <= 2; o <<= 1)
            #pragma unroll
            for (int m = 0; m < 2; ++m)
                #pragma unroll
                for (int gg = 0; gg < 2; ++gg)
                    tmax[m][gg] = fmaxf(tmax[m][gg],
                                        __shfl_xor_sync(0xffffffffu, tmax[m][gg], o));
        if (qd == 0)
            #pragma unroll
            for (int m = 0; m < 2; ++m)
                #pragma unroll
                for (int gg = 0; gg < 2; ++gg)
                    pmax[warpN*64 + warpM*32 + m*16 + g + gg*8] = tmax[m][gg];
        __syncthreads();   // b1

        float corr[2][2], tsum[2][2];
        #pragma unroll
        for (int m = 0; m < 2; ++m)
            #pragma unroll
            for (int gg = 0; gg < 2; ++gg) {
                const int r = warpM*32 + m*16 + g + gg*8;
                const float mx = fmaxf(pmax[r], pmax[64 + r]);
                const float mo = m_s[r];
                const float mn = fmaxf(mo, mx);
                corr[m][gg] = exp2f(mo - mn);
                float sum = 0.f;
                #pragma unroll
                for (int nf = 0; nf < 4; ++nf) {
                    const float p0 = exp2f(sacc[m][nf][gg*2]   - mn);
                    const float p1 = exp2f(sacc[m][nf][gg*2+1] - mn);
                    sum += p0 + p1;
                    __nv_bfloat16 h0,l0,h1,l1;
                    split_hl(p0, h0, l0);
                    split_hl(p1, h1, l1);
                    const int chunk = warpN*4 + nf;
                    *(uint32_t*)(Pa_c + foff(r, chunk)     + qd*4) = pack2bf(h0, h1);
                    *(uint32_t*)(Pa_c + foff(r, chunk + 8) + qd*4) = pack2bf(l0, l1);
                }
                tsum[m][gg] = sum;
            }
        #pragma unroll
        for (int o = 1; o <= 2; o <<= 1)
            #pragma unroll
            for (int m = 0; m < 2; ++m)
                #pragma unroll
                for (int gg = 0; gg < 2; ++gg)
                    tsum[m][gg] += __shfl_xor_sync(0xffffffffu, tsum[m][gg], o);
        if (qd == 0)
            #pragma unroll
            for (int m = 0; m < 2; ++m)
                #pragma unroll
                for (int gg = 0; gg < 2; ++gg)
                    psum[warpN*64 + warpM*32 + m*16 + g + gg*8] = tsum[m][gg];
        // rescale O
        #pragma unroll
        for (int m = 0; m < 2; ++m)
            #pragma unroll
            for (int nf = 0; nf < 4; ++nf) {
                oacc[m][nf][0] *= corr[m][0];
                oacc[m][nf][1] *= corr[m][0];
                oacc[m][nf][2] *= corr[m][1];
                oacc[m][nf][3] *= corr[m][1];
            }
        __syncthreads();   // b2: Pa + psum visible

        if (tid < 64) {
            const float mo = m_s[tid];
            const float mx = fmaxf(pmax[tid], pmax[64 + tid]);
            const float mn = fmaxf(mo, mx);
            const float cr = exp2f(mo - mn);
            l_s[tid] = l_s[tid] * cr + psum[tid] + psum[64 + tid];
            m_s[tid] = mn;
        }

        // ---- O += Pa @ Va^T (12 remapped k-steps) ----
        #pragma unroll
        for (int s = 0; s < 12; ++s) {
            uint32_t a[2][4], bfr[2][4];
            #pragma unroll
            for (int m = 0; m < 2; ++m)
                ldsm_x4(a[m][0], a[m][1], a[m][2], a[m][3],
                        pa_u + foff(warpM*32 + m*16 + (lane & 15), 2*AU[s] + (lane >> 4)));
            #pragma unroll
            for (int np = 0; np < 2; ++np)
                ldsm_x4(bfr[np][0], bfr[np][1], bfr[np][2], bfr[np][3],
                        va_u + foff(warpN*32 + np*16 + (lane & 15), 2*BU[s] + (lane >> 4)));
            #pragma unroll
            for (int m = 0; m < 2; ++m)
                #pragma unroll
                for (int nf = 0; nf < 4; ++nf)
                    mma_bf16(oacc[m][nf], a[m][0], a[m][1], a[m][2], a[m][3],
                             bfr[nf >> 1][nf & 1], bfr[nf >> 1][2 + (nf & 1)]);
        }
    }
    __syncthreads();   // final l_s visible

    const int b_ = bh >> 4, h = bh & 15;
    float inv[2][2];
    #pragma unroll
    for (int m = 0; m < 2; ++m)
        #pragma unroll
        for (int gg = 0; gg < 2; ++gg)
            inv[m][gg] = 1.f / l_s[warpM*32 + m*16 + g + gg*8];

    #pragma unroll
    for (int m = 0; m < 2; ++m)
        #pragma unroll
        for (int nf = 0; nf < 4; ++nf) {
            const int colL = warpN*32 + nf*8 + qd*2;
            #pragma unroll
            for (int gg = 0; gg < 2; ++gg) {
                const int r = warpM*32 + m*16 + g + gg*8;
                const float v0 = oacc[m][nf][gg*2]   * inv[m][gg];
                const float v1 = oacc[m][nf][gg*2+1] * inv[m][gg];
                __nv_bfloat16 h0,l0,h1,l1;
                split_hl(v0, h0, l0);
                split_hl(v1, h1, l1);
                const size_t ro = (size_t)(b_*SEQ + q0 + r) * KAUG + h*64 + colL;
                *(uint32_t*)(atta + ro)            = pack2bf(h0, h1);
                *(uint32_t*)(atta + ro + EMBED)    = pack2bf(l0, l1);
                *(uint32_t*)(atta + ro + 2*EMBED)  = pack2bf(h0, h1);
            }
        }
}

// ---------------------------------------------------------------------------
// Launch
// ---------------------------------------------------------------------------
extern "C" void kernel_launch(void* const* d_in, const int* in_sizes, int n_in,
                              void* d_out, int out_size)
{
    const float* x      = (const float*)d_in[0];
    const float* w_qkv  = (const float*)d_in[1];
    const float* b_qkv  = (const float*)d_in[2];
    const float* w_proj = (const float*)d_in[3];
    const float* b_proj = (const float*)d_in[4];
    float* out = (float*)d_out;

    __nv_bfloat16 *xa, *atta, *wqkvT, *wprojT, *qh, *ql, *kh, *kl, *vh, *vl;
    cudaGetSymbolAddress((void**)&xa,     g_xa);
    cudaGetSymbolAddress((void**)&atta,   g_atta);
    cudaGetSymbolAddress((void**)&wqkvT,  g_wqkvT);
    cudaGetSymbolAddress((void**)&wprojT, g_wprojT);
    cudaGetSymbolAddress((void**)&qh,     g_qhi);
    cudaGetSymbolAddress((void**)&ql,     g_qlo);
    cudaGetSymbolAddress((void**)&kh,     g_khi);
    cudaGetSymbolAddress((void**)&kl,     g_klo);
    cudaGetSymbolAddress((void**)&vh,     g_vhiT);
    cudaGetSymbolAddress((void**)&vl,     g_vloT);

    cudaFuncSetAttribute(flash_mma_kernel,
                         cudaFuncAttributeMaxDynamicSharedMemorySize, FLASH_SMEM);

    split_x_kernel<<<MROWS, 256>>>(x, xa);
    transpose_split_kernel<<<dim3(QKV_N/32, EMBED/32), dim3(32,8)>>>(w_qkv, wqkvT, EMBED, QKV_N);
    transpose_split_kernel<<<dim3(EMBED/32, EMBED/32), dim3(32,8)>>>(w_proj, wprojT, EMBED, EMBED);

    // k1: qkv GEMM -> split planes
    mma_gemm_kernel<1><<<dim3(QKV_N/128, MROWS/128), 256>>>(
        xa, wqkvT, b_qkv, nullptr, qh, ql, kh, kl, vh, vl, MROWS, QKV_N, KAUG);

    // k2: flash attention (HMMA) -> augmented atta
    flash_mma_kernel<<<dim3(SEQ/64, NBH), 128, FLASH_SMEM>>>(qh, ql, kh, kl, vh, vl, atta);

    // k3: out = atta @ wprojT^T + b_proj
    mma_gemm_kernel<0><<<dim3(EMBED/128, MROWS/128), 256>>>(
        atta, wprojT, b_proj, out, nullptr, nullptr, nullptr, nullptr, nullptr, nullptr,
        MROWS, EMBED, KAUG);
}

// round 6
// speedup vs baseline: 2.9210x; 1.0856x over previous
#include <cuda_runtime.h>
#include <cuda_bf16.h>
#include <cstdint>

// ===========================================================================
// MultiHeadSelfAttention, sm_100 (mma.sync HMMA path everywhere).
//   s1: split x -> xa bf16 [8192 x 3072] ([hi|lo|hi])
//   s2/s3: transpose+split weights -> [N x 3K] bf16 ([hi|hi|lo])
//   k1: qkv GEMM (4-stage cp.async) -> split planes qhi/qlo,khi/klo [bh][n][64],
//       vhiT/vloT [bh][d][n]. Q pre-scaled by 0.125*log2(e).
//   k2: flash attention on HMMA, double-buffered K/V prefetch,
//       chunk-remapped split products; writes augmented atta.
//   k3: out = atta @ wprojT^T + b_proj (4-stage pipeline).
// ===========================================================================

#define EMBED   1024
#define HEADS   16
#define HDIM    64
#define BATCH   4
#define SEQ     2048
#define MROWS   (BATCH * SEQ)     // 8192
#define QKV_N   (3 * EMBED)       // 3072
#define KAUG    (3 * EMBED)       // 3072
#define NBH     (BATCH * HEADS)   // 64
#define QSC     (0.125f * 1.44269504f)

__device__ __nv_bfloat16  g_xa[(size_t)MROWS * KAUG];       // 48 MB
__device__ __nv_bfloat16  g_atta[(size_t)MROWS * KAUG];     // 48 MB
__device__ __nv_bfloat16  g_wqkvT[(size_t)QKV_N * KAUG];    // 18 MB
__device__ __nv_bfloat16  g_wprojT[(size_t)EMBED * KAUG];   //  6 MB
__device__ __nv_bfloat16  g_qhi[(size_t)NBH * SEQ * HDIM];
__device__ __nv_bfloat16  g_qlo[(size_t)NBH * SEQ * HDIM];
__device__ __nv_bfloat16  g_khi[(size_t)NBH * SEQ * HDIM];
__device__ __nv_bfloat16  g_klo[(size_t)NBH * SEQ * HDIM];
__device__ __nv_bfloat16  g_vhiT[(size_t)NBH * HDIM * SEQ];
__device__ __nv_bfloat16  g_vloT[(size_t)NBH * HDIM * SEQ];

// ---------------------------------------------------------------------------
// helpers
// ---------------------------------------------------------------------------
__device__ __forceinline__ uint32_t smem_u32(const void* p) {
    uint32_t a;
    asm("{ .reg .u64 t; cvta.to.shared.u64 t, %1; cvt.u32.u64 %0, t; }"
        : "=r"(a) : "l"(p));
    return a;
}
__device__ __forceinline__ void ldsm_x4(uint32_t& r0, uint32_t& r1,
                                        uint32_t& r2, uint32_t& r3, uint32_t addr) {
    asm volatile("ldmatrix.sync.aligned.m8n8.x4.shared.b16 {%0,%1,%2,%3}, [%4];"
                 : "=r"(r0), "=r"(r1), "=r"(r2), "=r"(r3) : "r"(addr));
}
__device__ __forceinline__ void mma_bf16(float* c, uint32_t a0, uint32_t a1,
                                         uint32_t a2, uint32_t a3,
                                         uint32_t b0, uint32_t b1) {
    asm volatile(
        "mma.sync.aligned.m16n8k16.row.col.f32.bf16.bf16.f32 "
        "{%0,%1,%2,%3}, {%4,%5,%6,%7}, {%8,%9}, {%0,%1,%2,%3};"
        : "+f"(c[0]), "+f"(c[1]), "+f"(c[2]), "+f"(c[3])
        : "r"(a0), "r"(a1), "r"(a2), "r"(a3), "r"(b0), "r"(b1));
}
#define CP_ASYNC16(smem, gptr) \
    asm volatile("cp.async.cg.shared.global [%0], [%1], 16;" :: "r"(smem), "l"(gptr))
#define CP_COMMIT() asm volatile("cp.async.commit_group;" ::: "memory")
#define CP_WAIT1()  asm volatile("cp.async.wait_group 1;" ::: "memory")
#define CP_WAIT2()  asm volatile("cp.async.wait_group 2;" ::: "memory")

// GEMM tile (64B rows): chunk' = chunk ^ ((row>>1)&3)
__device__ __forceinline__ uint32_t tile_off(int r, int c) {
    return (uint32_t)(r * 64 + ((c ^ ((r >> 1) & 3)) << 4));
}
// Flash tile (256B rows, 16 chunks): chunk' = chunk ^ (row & 7)
__device__ __forceinline__ uint32_t foff(int r, int c) {
    return (uint32_t)(r * 256 + ((c ^ (r & 7)) << 4));
}

__device__ __forceinline__ void split_hl(float v, __nv_bfloat16& hi, __nv_bfloat16& lo) {
    hi = __float2bfloat16_rn(v);
    lo = __float2bfloat16_rn(v - __bfloat162float(hi));
}
__device__ __forceinline__ uint32_t pack2bf(__nv_bfloat16 a, __nv_bfloat16 b) {
    __nv_bfloat162 p(a, b);
    return *reinterpret_cast<uint32_t*>(&p);
}

// ---------------------------------------------------------------------------
// s1: split x -> xa [hi | lo | hi]
// ---------------------------------------------------------------------------
__global__ void __launch_bounds__(256)
split_x_kernel(const float* __restrict__ x, __nv_bfloat16* __restrict__ xa)
{
    const int row = blockIdx.x;
    const int c = threadIdx.x * 4;
    float4 v = *(const float4*)(x + (size_t)row * EMBED + c);
    __nv_bfloat16 h0,h1,h2,h3,l0,l1,l2,l3;
    split_hl(v.x, h0, l0); split_hl(v.y, h1, l1);
    split_hl(v.z, h2, l2); split_hl(v.w, h3, l3);
    const size_t o = (size_t)row * KAUG + c;
    uint2 uh; uh.x = pack2bf(h0,h1); uh.y = pack2bf(h2,h3);
    uint2 ul; ul.x = pack2bf(l0,l1); ul.y = pack2bf(l2,l3);
    *(uint2*)(xa + o)           = uh;
    *(uint2*)(xa + o + EMBED)   = ul;
    *(uint2*)(xa + o + 2*EMBED) = uh;
}

// ---------------------------------------------------------------------------
// s2/s3: W [K x N] fp32 -> Bp [N x 3K] bf16 ([hi | hi | lo])
// ---------------------------------------------------------------------------
__global__ void __launch_bounds__(256)
transpose_split_kernel(const float* __restrict__ W, __nv_bfloat16* __restrict__ Bp,
                       int K, int N)
{
    __shared__ float t[32][33];
    const int n0 = blockIdx.x * 32, k0 = blockIdx.y * 32;
    const int tx = threadIdx.x, ty = threadIdx.y;
    #pragma unroll
    for (int i = 0; i < 4; ++i)
        t[ty + 8*i][tx] = W[(size_t)(k0 + ty + 8*i) * N + n0 + tx];
    __syncthreads();
    #pragma unroll
    for (int i = 0; i < 4; ++i) {
        const int n = ty + 8*i;
        float v = t[tx][n];
        __nv_bfloat16 hi, lo;
        split_hl(v, hi, lo);
        const size_t ro = (size_t)(n0 + n) * (3*K);
        Bp[ro + k0 + tx]       = hi;
        Bp[ro + K + k0 + tx]   = hi;
        Bp[ro + 2*K + k0 + tx] = lo;
    }
}

// ---------------------------------------------------------------------------
// HMMA GEMM: 128x128x32 tile, 8 warps (2x4), 4-stage cp.async pipeline.
// dyn smem = 4 stages x (8KB A + 8KB B) = 64KB.
// MODE 0: C = A@B^T + bias.  MODE 1: qkv epilogue -> split planes.
// ---------------------------------------------------------------------------
#define GEMM_SMEM 65536

template<int MODE>
__global__ void __launch_bounds__(256)
mma_gemm_kernel(const __nv_bfloat16* __restrict__ A, const __nv_bfloat16* __restrict__ B,
                const float* __restrict__ bias, float* __restrict__ C,
                __nv_bfloat16* __restrict__ qh, __nv_bfloat16* __restrict__ ql,
                __nv_bfloat16* __restrict__ kh, __nv_bfloat16* __restrict__ kl,
                __nv_bfloat16* __restrict__ vh, __nv_bfloat16* __restrict__ vl,
                int M, int N, int K)
{
    extern __shared__ __align__(1024) uint8_t dsm[];

    const int tid  = threadIdx.x;
    const int wid  = tid >> 5;
    const int lane = tid & 31;
    const int bx = blockIdx.x, by = blockIdx.y;
    const int warp_m = wid & 1;
    const int warp_n = wid >> 1;
    const uint32_t sbase = smem_u32(dsm);

    const size_t Ks = (size_t)K;
    const __nv_bfloat16* Ab = A + (size_t)(by * 128) * Ks;
    const __nv_bfloat16* Bb = B + (size_t)(bx * 128) * Ks;

    // per-thread load geometry (fixed): 2 chunks A + 2 chunks B per stage
    const int lr0 = tid >> 2,        lc0 = tid & 3;
    const int lr1 = (tid + 256) >> 2, lc1 = (tid + 256) & 3;
    const __nv_bfloat16* Ag0 = Ab + (size_t)lr0 * Ks + lc0 * 8;
    const __nv_bfloat16* Ag1 = Ab + (size_t)lr1 * Ks + lc1 * 8;
    const __nv_bfloat16* Bg0 = Bb + (size_t)lr0 * Ks + lc0 * 8;
    const __nv_bfloat16* Bg1 = Bb + (size_t)lr1 * Ks + lc1 * 8;
    const uint32_t sA0 = tile_off(lr0, lc0), sA1 = tile_off(lr1, lc1);

    auto load_stage = [&](int kt, int st) {
        const int k0 = kt * 32;
        const uint32_t s = sbase + st * 16384;
        CP_ASYNC16(s + sA0,        Ag0 + k0);
        CP_ASYNC16(s + sA1,        Ag1 + k0);
        CP_ASYNC16(s + 8192 + sA0, Bg0 + k0);
        CP_ASYNC16(s + 8192 + sA1, Bg1 + k0);
    };

    // hoisted ldsm offsets (lane-invariant across iterations)
    uint32_t aoff[2][4], boff[2][2];
    #pragma unroll
    for (int ks = 0; ks < 2; ++ks) {
        #pragma unroll
        for (int mf = 0; mf < 4; ++mf)
            aoff[ks][mf] = tile_off(warp_m * 64 + mf * 16 + (lane & 15),
                                    ks * 2 + (lane >> 4));
        #pragma unroll
        for (int np = 0; np < 2; ++np)
            boff[ks][np] = 8192 + tile_off(warp_n * 32 + np * 16 + (lane & 15),
                                           ks * 2 + (lane >> 4));
    }

    float acc[4][4][4] = {};
    const int T = K >> 5;      // 96

    // prologue: stages 0..2
    load_stage(0, 0); CP_COMMIT();
    load_stage(1, 1); CP_COMMIT();
    load_stage(2, 2); CP_COMMIT();

    for (int t = 0; t < T; ++t) {
        CP_WAIT2();
        __syncthreads();

        const uint32_t st = sbase + (t & 3) * 16384;
        #pragma unroll
        for (int ks = 0; ks < 2; ++ks) {
            uint32_t a[4][4];
            #pragma unroll
            for (int mf = 0; mf < 4; ++mf)
                ldsm_x4(a[mf][0], a[mf][1], a[mf][2], a[mf][3], st + aoff[ks][mf]);
            uint32_t b[2][4];
            #pragma unroll
            for (int np = 0; np < 2; ++np)
                ldsm_x4(b[np][0], b[np][1], b[np][2], b[np][3], st + boff[ks][np]);
            #pragma unroll
            for (int mf = 0; mf < 4; ++mf)
                #pragma unroll
                for (int nf = 0; nf < 4; ++nf) {
                    const int np = nf >> 1, hl = nf & 1;
                    mma_bf16(acc[mf][nf], a[mf][0], a[mf][1], a[mf][2], a[mf][3],
                             b[np][0 + hl], b[np][2 + hl]);
                }
        }

        if (t + 3 < T) load_stage(t + 3, (t + 3) & 3);
        CP_COMMIT();
    }

    const int g  = lane >> 2;
    const int cl = (lane & 3) * 2;
    #pragma unroll
    for (int mf = 0; mf < 4; ++mf) {
        const int mrow = by * 128 + warp_m * 64 + mf * 16 + g;
        #pragma unroll
        for (int nf = 0; nf < 4; ++nf) {
            const int col = bx * 128 + warp_n * 32 + nf * 8 + cl;
            const float b0 = bias[col], b1 = bias[col + 1];
            float v[4] = { acc[mf][nf][0] + b0, acc[mf][nf][1] + b1,
                           acc[mf][nf][2] + b0, acc[mf][nf][3] + b1 };
            if constexpr (MODE == 0) {
                *(float2*)(C + (size_t)mrow * N + col)       = make_float2(v[0], v[1]);
                *(float2*)(C + (size_t)(mrow + 8) * N + col) = make_float2(v[2], v[3]);
            } else {
                const int which = col >> 10;           // 0=q 1=k 2=v
                const int h = (col >> 6) & 15;
                const int d = col & 63;
                const int bb = mrow >> 11;
                const int n0 = mrow & 2047;
                if (which == 0) { v[0]*=QSC; v[1]*=QSC; v[2]*=QSC; v[3]*=QSC; }
                #pragma unroll
                for (int rr = 0; rr < 2; ++rr) {
                    const int n = n0 + rr * 8;
                    __nv_bfloat16 h0,l0,h1,l1;
                    split_hl(v[rr*2+0], h0, l0);
                    split_hl(v[rr*2+1], h1, l1);
                    if (which < 2) {
                        const size_t base = (size_t)(bb*16 + h) * (SEQ*HDIM)
                                          + (size_t)n * HDIM + d;
                        __nv_bfloat16* PH = which ? kh : qh;
                        __nv_bfloat16* PL = which ? kl : ql;
                        *(uint32_t*)(PH + base) = pack2bf(h0, h1);
                        *(uint32_t*)(PL + base) = pack2bf(l0, l1);
                    } else {
                        const size_t base = (size_t)(bb*16 + h) * (SEQ*HDIM)
                                          + (size_t)d * SEQ + n;
                        vh[base]       = h0;  vh[base + SEQ] = h1;
                        vl[base]       = l0;  vl[base + SEQ] = l1;
                    }
                }
            }
        }
    }
}

// ---------------------------------------------------------------------------
// k2: flash attention on HMMA, double-buffered K/V.
// 64 queries/block, 128 thr (4 warps 2x2).
// smem: Qa 16K | Ka[2] 32K | Va[2] 32K | Pa 16K | stats 1.5K = 99840 B.
// ---------------------------------------------------------------------------
#define FLASH_SMEM (98304 + 1536)

__global__ void __launch_bounds__(128)
flash_mma_kernel(const __nv_bfloat16* __restrict__ qhi, const __nv_bfloat16* __restrict__ qlo,
                 const __nv_bfloat16* __restrict__ khi, const __nv_bfloat16* __restrict__ klo,
                 const __nv_bfloat16* __restrict__ vhiT, const __nv_bfloat16* __restrict__ vloT,
                 __nv_bfloat16* __restrict__ atta)
{
    extern __shared__ __align__(1024) uint8_t fsm[];
    uint8_t* Pa_c = fsm + 81920;
    float* pmax = (float*)(fsm + 98304);     // [2][64]
    float* psum = pmax + 128;                // [2][64]
    float* m_s  = psum + 128;                // [64]
    float* l_s  = m_s + 64;                  // [64]

    const uint32_t sbase = smem_u32(fsm);
    const uint32_t qa_u = sbase;
    const uint32_t ka_u0 = sbase + 16384;    // + buf*16384
    const uint32_t va_u0 = sbase + 49152;    // + buf*16384
    const uint32_t pa_u  = sbase + 81920;

    const int tid  = threadIdx.x;
    const int wid  = tid >> 5;
    const int lane = tid & 31;
    const int warpM = wid >> 1;
    const int warpN = wid & 1;
    const int g  = lane >> 2;
    const int qd = lane & 3;

    const int qt = blockIdx.x, bh = blockIdx.y;
    const int q0 = qt * 64;

    // Q load (group 0)
    {
        const size_t qbase = ((size_t)bh * SEQ + q0) * HDIM;
        for (int i = tid; i < 1024; i += 128) {
            const int r = i >> 4, c = i & 15;
            CP_ASYNC16(qa_u + foff(r, c),
                       (c < 8 ? qhi : qlo) + qbase + r * HDIM + (c & 7) * 8);
        }
        CP_COMMIT();
    }

    auto load_kv = [&](int kt, int buf) {
        const size_t kbase = ((size_t)bh * SEQ + kt * 64) * HDIM;
        const uint32_t ka = ka_u0 + buf * 16384, va = va_u0 + buf * 16384;
        for (int i = tid; i < 1024; i += 128) {
            const int r = i >> 4, c = i & 15;
            CP_ASYNC16(ka + foff(r, c),
                       (c < 8 ? khi : klo) + kbase + r * HDIM + (c & 7) * 8);
            CP_ASYNC16(va + foff(r, c),
                       (c < 8 ? vhiT : vloT) + (size_t)(bh * HDIM + r) * SEQ
                                             + kt * 64 + (c & 7) * 8);
        }
    };

    load_kv(0, 0); CP_COMMIT();
    if (tid < 64) { m_s[tid] = -1e30f; l_s[tid] = 0.f; }

    const int AU[12] = {0,1,2,3, 4,5,6,7, 0,1,2,3};
    const int BU[12] = {0,1,2,3, 0,1,2,3, 4,5,6,7};

    float oacc[2][4][4] = {};

    for (int kt = 0; kt < 32; ++kt) {
        const int buf = kt & 1;
        __syncthreads();              // (a) prior iter fully done (other buf, Pa free)
        if (kt + 1 < 32) load_kv(kt + 1, buf ^ 1);
        CP_COMMIT();
        CP_WAIT1();                   // KV(kt) landed (mine)
        __syncthreads();              // (b) everyone's KV(kt) visible

        const uint32_t ka_u = ka_u0 + buf * 16384;
        const uint32_t va_u = va_u0 + buf * 16384;

        // ---- S = Qa @ Ka^T ----
        float sacc[2][4][4] = {};
        #pragma unroll
        for (int s = 0; s < 12; ++s) {
            uint32_t a[2][4], bfr[2][4];
            #pragma unroll
            for (int m = 0; m < 2; ++m)
                ldsm_x4(a[m][0], a[m][1], a[m][2], a[m][3],
                        qa_u + foff(warpM*32 + m*16 + (lane & 15), 2*AU[s] + (lane >> 4)));
            #pragma unroll
            for (int np = 0; np < 2; ++np)
                ldsm_x4(bfr[np][0], bfr[np][1], bfr[np][2], bfr[np][3],
                        ka_u + foff(warpN*32 + np*16 + (lane & 15), 2*BU[s] + (lane >> 4)));
            #pragma unroll
            for (int m = 0; m < 2; ++m)
                #pragma unroll
                for (int nf = 0; nf < 4; ++nf)
                    mma_bf16(sacc[m][nf], a[m][0], a[m][1], a[m][2], a[m][3],
                             bfr[nf >> 1][nf & 1], bfr[nf >> 1][2 + (nf & 1)]);
        }

        // ---- softmax ----
        float tmax[2][2];
        #pragma unroll
        for (int m = 0; m < 2; ++m)
            #pragma unroll
            for (int gg = 0; gg < 2; ++gg) {
                float mx = -1e30f;
                #pragma unroll
                for (int nf = 0; nf < 4; ++nf)
                    mx = fmaxf(mx, fmaxf(sacc[m][nf][gg*2], sacc[m][nf][gg*2+1]));
                tmax[m][gg] = mx;
            }
        #pragma unroll
        for (int o = 1; o <= 2; o <<= 1)
            #pragma unroll
            for (int m = 0; m < 2; ++m)
                #pragma unroll
                for (int gg = 0; gg < 2; ++gg)
                    tmax[m][gg] = fmaxf(tmax[m][gg],
                                        __shfl_xor_sync(0xffffffffu, tmax[m][gg], o));
        if (qd == 0)
            #pragma unroll
            for (int m = 0; m < 2; ++m)
                #pragma unroll
                for (int gg = 0; gg < 2; ++gg)
                    pmax[warpN*64 + warpM*32 + m*16 + g + gg*8] = tmax[m][gg];
        __syncthreads();   // b1

        float corr[2][2], tsum[2][2];
        #pragma unroll
        for (int m = 0; m < 2; ++m)
            #pragma unroll
            for (int gg = 0; gg < 2; ++gg) {
                const int r = warpM*32 + m*16 + g + gg*8;
                const float mx = fmaxf(pmax[r], pmax[64 + r]);
                const float mo = m_s[r];
                const float mn = fmaxf(mo, mx);
                corr[m][gg] = exp2f(mo - mn);
                float sum = 0.f;
                #pragma unroll
                for (int nf = 0; nf < 4; ++nf) {
                    const float p0 = exp2f(sacc[m][nf][gg*2]   - mn);
                    const float p1 = exp2f(sacc[m][nf][gg*2+1] - mn);
                    sum += p0 + p1;
                    __nv_bfloat16 h0,l0,h1,l1;
                    split_hl(p0, h0, l0);
                    split_hl(p1, h1, l1);
                    const int chunk = warpN*4 + nf;
                    *(uint32_t*)(Pa_c + foff(r, chunk)     + qd*4) = pack2bf(h0, h1);
                    *(uint32_t*)(Pa_c + foff(r, chunk + 8) + qd*4) = pack2bf(l0, l1);
                }
                tsum[m][gg] = sum;
            }
        #pragma unroll
        for (int o = 1; o <= 2; o <<= 1)
            #pragma unroll
            for (int m = 0; m < 2; ++m)
                #pragma unroll
                for (int gg = 0; gg < 2; ++gg)
                    tsum[m][gg] += __shfl_xor_sync(0xffffffffu, tsum[m][gg], o);
        if (qd == 0)
            #pragma unroll
            for (int m = 0; m < 2; ++m)
                #pragma unroll
                for (int gg = 0; gg < 2; ++gg)
                    psum[warpN*64 + warpM*32 + m*16 + g + gg*8] = tsum[m][gg];
        #pragma unroll
        for (int m = 0; m < 2; ++m)
            #pragma unroll
            for (int nf = 0; nf < 4; ++nf) {
                oacc[m][nf][0] *= corr[m][0];
                oacc[m][nf][1] *= corr[m][0];
                oacc[m][nf][2] *= corr[m][1];
                oacc[m][nf][3] *= corr[m][1];
            }
        __syncthreads();   // b2: Pa + psum visible

        if (tid < 64) {
            const float mo = m_s[tid];
            const float mx = fmaxf(pmax[tid], pmax[64 + tid]);
            const float mn = fmaxf(mo, mx);
            const float cr = exp2f(mo - mn);
            l_s[tid] = l_s[tid] * cr + psum[tid] + psum[64 + tid];
            m_s[tid] = mn;
        }

        // ---- O += Pa @ Va^T ----
        #pragma unroll
        for (int s = 0; s < 12; ++s) {
            uint32_t a[2][4], bfr[2][4];
            #pragma unroll
            for (int m = 0; m < 2; ++m)
                ldsm_x4(a[m][0], a[m][1], a[m][2], a[m][3],
                        pa_u + foff(warpM*32 + m*16 + (lane & 15), 2*AU[s] + (lane >> 4)));
            #pragma unroll
            for (int np = 0; np < 2; ++np)
                ldsm_x4(bfr[np][0], bfr[np][1], bfr[np][2], bfr[np][3],
                        va_u + foff(warpN*32 + np*16 + (lane & 15), 2*BU[s] + (lane >> 4)));
            #pragma unroll
            for (int m = 0; m < 2; ++m)
                #pragma unroll
                for (int nf = 0; nf < 4; ++nf)
                    mma_bf16(oacc[m][nf], a[m][0], a[m][1], a[m][2], a[m][3],
                             bfr[nf >> 1][nf & 1], bfr[nf >> 1][2 + (nf & 1)]);
        }
    }
    __syncthreads();

    const int b_ = bh >> 4, h = bh & 15;
    float inv[2][2];
    #pragma unroll
    for (int m = 0; m < 2; ++m)
        #pragma unroll
        for (int gg = 0; gg < 2; ++gg)
            inv[m][gg] = 1.f / l_s[warpM*32 + m*16 + g + gg*8];

    #pragma unroll
    for (int m = 0; m < 2; ++m)
        #pragma unroll
        for (int nf = 0; nf < 4; ++nf) {
            const int colL = warpN*32 + nf*8 + qd*2;
            #pragma unroll
            for (int gg = 0; gg < 2; ++gg) {
                const int r = warpM*32 + m*16 + g + gg*8;
                const float v0 = oacc[m][nf][gg*2]   * inv[m][gg];
                const float v1 = oacc[m][nf][gg*2+1] * inv[m][gg];
                __nv_bfloat16 h0,l0,h1,l1;
                split_hl(v0, h0, l0);
                split_hl(v1, h1, l1);
                const size_t ro = (size_t)(b_*SEQ + q0 + r) * KAUG + h*64 + colL;
                *(uint32_t*)(atta + ro)            = pack2bf(h0, h1);
                *(uint32_t*)(atta + ro + EMBED)    = pack2bf(l0, l1);
                *(uint32_t*)(atta + ro + 2*EMBED)  = pack2bf(h0, h1);
            }
        }
}

// ---------------------------------------------------------------------------
// Launch
// ---------------------------------------------------------------------------
extern "C" void kernel_launch(void* const* d_in, const int* in_sizes, int n_in,
                              void* d_out, int out_size)
{
    const float* x      = (const float*)d_in[0];
    const float* w_qkv  = (const float*)d_in[1];
    const float* b_qkv  = (const float*)d_in[2];
    const float* w_proj = (const float*)d_in[3];
    const float* b_proj = (const float*)d_in[4];
    float* out = (float*)d_out;

    __nv_bfloat16 *xa, *atta, *wqkvT, *wprojT, *qh, *ql, *kh, *kl, *vh, *vl;
    cudaGetSymbolAddress((void**)&xa,     g_xa);
    cudaGetSymbolAddress((void**)&atta,   g_atta);
    cudaGetSymbolAddress((void**)&wqkvT,  g_wqkvT);
    cudaGetSymbolAddress((void**)&wprojT, g_wprojT);
    cudaGetSymbolAddress((void**)&qh,     g_qhi);
    cudaGetSymbolAddress((void**)&ql,     g_qlo);
    cudaGetSymbolAddress((void**)&kh,     g_khi);
    cudaGetSymbolAddress((void**)&kl,     g_klo);
    cudaGetSymbolAddress((void**)&vh,     g_vhiT);
    cudaGetSymbolAddress((void**)&vl,     g_vloT);

    cudaFuncSetAttribute(mma_gemm_kernel<1>,
                         cudaFuncAttributeMaxDynamicSharedMemorySize, GEMM_SMEM);
    cudaFuncSetAttribute(mma_gemm_kernel<0>,
                         cudaFuncAttributeMaxDynamicSharedMemorySize, GEMM_SMEM);
    cudaFuncSetAttribute(flash_mma_kernel,
                         cudaFuncAttributeMaxDynamicSharedMemorySize, FLASH_SMEM);

    split_x_kernel<<<MROWS, 256>>>(x, xa);
    transpose_split_kernel<<<dim3(QKV_N/32, EMBED/32), dim3(32,8)>>>(w_qkv, wqkvT, EMBED, QKV_N);
    transpose_split_kernel<<<dim3(EMBED/32, EMBED/32), dim3(32,8)>>>(w_proj, wprojT, EMBED, EMBED);

    mma_gemm_kernel<1><<<dim3(QKV_N/128, MROWS/128), 256, GEMM_SMEM>>>(
        xa, wqkvT, b_qkv, nullptr, qh, ql, kh, kl, vh, vl, MROWS, QKV_N, KAUG);

    flash_mma_kernel<<<dim3(SEQ/64, NBH), 128, FLASH_SMEM>>>(qh, ql, kh, kl, vh, vl, atta);

    mma_gemm_kernel<0><<<dim3(EMBED/128, MROWS/128), 256, GEMM_SMEM>>>(
        atta, wprojT, b_proj, out, nullptr, nullptr, nullptr, nullptr, nullptr, nullptr,
        MROWS, EMBED, KAUG);
}